// round 1
// baseline (speedup 1.0000x reference)
#include <cuda_runtime.h>

#define KK 9
#define START_TAG 7
#define STOP_TAG 8
#define PD 8
#define FULLM 0xFFFFFFFFu

// deterministic per-sentence partials (no atomics) — B <= 8192 supported
__device__ float g_partial[8192];

__device__ __forceinline__ float dot9(const float* c, const float* v) {
    // 2-way chains: ~20cy latency, 10 instrs
    float d0 = c[0] * v[0];
    float d1 = c[1] * v[1];
    d0 = fmaf(c[2], v[2], d0);
    d1 = fmaf(c[3], v[3], d1);
    d0 = fmaf(c[4], v[4], d0);
    d1 = fmaf(c[5], v[5], d1);
    d0 = fmaf(c[6], v[6], d0);
    d1 = fmaf(c[7], v[7], d1);
    d0 = fmaf(c[8], v[8], d0);
    return d0 + d1;
}

__device__ __forceinline__ void scan_step(float fv, bool act, const float* c,
                                          float* vec, float& s, int& eacc,
                                          int base) {
    float d  = dot9(c, vec);
    float ef = __expf(fv);
    // power-of-two rescale factor from current vec magnitude (exact)
    float m = fmaxf(fmaxf(fmaxf(fmaxf(vec[0], vec[1]), fmaxf(vec[2], vec[3])),
                          fmaxf(fmaxf(vec[4], vec[5]), fmaxf(vec[6], vec[7]))),
                    vec[8]);
    int   e     = ((__float_as_int(m) >> 23) & 0xFF) - 127;
    float scale = __int_as_float((127 - e) << 23);
    if (act) {
        s = d * ef * scale;
        eacc += e;
    }
#pragma unroll
    for (int k = 0; k < KK; ++k) vec[k] = __shfl_sync(FULLM, s, base + k);
}

__global__ void __launch_bounds__(32) crf_kernel(
    const float* __restrict__ feats, const float* __restrict__ trans,
    const int* __restrict__ tags, const int* __restrict__ lengths, int T) {
    const int b    = blockIdx.x;
    const int lane = threadIdx.x;
    const int len  = lengths[b];
    const float* __restrict__ f  = feats + (long)b * T * KK;
    const int* __restrict__  tg  = tags + (long)b * T;

    // ---------------- gold path score (all 32 lanes, parallel over t) -------
    float gold = 0.f;
    for (int t = lane; t < len; t += 32) {
        int cur  = tg[t];
        int prev = (t == 0) ? START_TAG : tg[t - 1];
        gold += trans[cur * KK + prev] + f[t * KK + cur];
    }
    if (lane == 0) gold += trans[STOP_TAG * KK + tg[len - 1]];
#pragma unroll
    for (int o = 16; o; o >>= 1) gold += __shfl_xor_sync(FULLM, gold, o);

    // ---------------- bidirectional exp-domain forward algorithm ------------
    // lanes 0..8  : forward scan over t = 0 .. NT-1        (rows of E)
    // lanes 16..24: backward scan over t = len-1 .. NT     (cols of E)
    const bool isb  = (lane & 16) != 0;
    const int  idx  = lane & 15;
    const int  base = lane & 16;
    const bool live = idx < KK;

    float c[KK];
#pragma unroll
    for (int k = 0; k < KK; ++k) {
        int   r  = isb ? k : idx;
        int   cc = isb ? idx : k;
        float tv = live ? trans[r * KK + cc] : 0.f;
        c[k]     = __expf(tv);  // exp(-10000) == 0 exactly in fp32
    }

    const int NT   = len >> 1;       // forward step count (== loop trips)
    const int nbm1 = len - NT - 1;   // backward active trips inside loop

    float s;
    if (!isb) {
        s = (idx == START_TAG) ? 1.f : 0.f;
    } else {
        float tv = live ? trans[STOP_TAG * KK + idx] : 0.f;
        float fv = live ? f[(len - 1) * KK + idx] : 0.f;
        s        = live ? __expf(tv + fv) : 0.f;  // r0 = v_init * ef(len-1)
    }
    int   eacc = 0;
    float vec[KK];
#pragma unroll
    for (int k = 0; k < KK; ++k) vec[k] = __shfl_sync(FULLM, s, base + k);

    // software prefetch ring: PD steps ahead (covers L2-hit latency)
    float buf[PD];
#pragma unroll
    for (int u = 0; u < PD; ++u) {
        int t  = isb ? (len - 2 - u) : u;
        buf[u] = (live && t >= 0 && t < len) ? f[t * KK + idx] : 0.f;
    }

    const int nfull = NT & ~(PD - 1);
    for (int n0 = 0; n0 < nfull; n0 += PD) {
#pragma unroll
        for (int u = 0; u < PD; ++u) {
            int   n  = n0 + u;
            float fv = buf[u];
            int   tp = isb ? (len - 2 - (n + PD)) : (n + PD);
            buf[u]   = (live && tp >= 0 && tp < len) ? f[tp * KK + idx] : 0.f;
            bool act = (!isb) || (n < nbm1);
            scan_step(fv, act, c, vec, s, eacc, base);
        }
    }
    for (int n = nfull; n < NT; ++n) {  // short tail: reload (L1-hot)
        int   t  = isb ? (len - 2 - n) : n;
        float fv = (live && t >= 0 && t < len) ? f[t * KK + idx] : 0.f;
        bool act = (!isb) || (n < nbm1);
        scan_step(fv, act, c, vec, s, eacc, base);
    }

    // backward needs one final matrix application (no emission factor)
    float vfin = dot9(c, vec);
    // pull forward's u_i into backward lanes, combine: S = sum_i u_i * v_i
    float ui = __shfl_sync(FULLM, s, idx);
    float p  = (isb && live) ? vfin * ui : 0.f;
#pragma unroll
    for (int o = 16; o; o >>= 1) p += __shfl_xor_sync(FULLM, p, o);
    int eaf = __shfl_sync(FULLM, eacc, 0);
    int eab = __shfl_sync(FULLM, eacc, 16);

    if (lane == 0 && b < 8192) {
        float fwd    = (__log2f(p) + (float)(eaf + eab)) * 0.6931471805599453f;
        g_partial[b] = fwd - gold;
    }
}

__global__ void reduce_kernel(float* __restrict__ out, int B) {
    int   tid = threadIdx.x;
    float v   = 0.f;
    for (int i = tid; i < B; i += blockDim.x) v += g_partial[i];
#pragma unroll
    for (int o = 16; o; o >>= 1) v += __shfl_xor_sync(FULLM, v, o);
    __shared__ float sh[32];
    if ((tid & 31) == 0) sh[tid >> 5] = v;
    __syncthreads();
    if (tid < 32) {
        float w = (tid < (int)(blockDim.x >> 5)) ? sh[tid] : 0.f;
#pragma unroll
        for (int o = 16; o; o >>= 1) w += __shfl_xor_sync(FULLM, w, o);
        if (tid == 0) out[0] = w / (float)B;
    }
}

extern "C" void kernel_launch(void* const* d_in, const int* in_sizes, int n_in,
                              void* d_out, int out_size) {
    const float* feats   = (const float*)d_in[0];
    const float* trans   = (const float*)d_in[1];
    const int*   tags    = (const int*)d_in[2];
    const int*   lengths = (const int*)d_in[3];
    int B = in_sizes[3];
    int T = in_sizes[2] / B;
    crf_kernel<<<B, 32>>>(feats, trans, tags, lengths, T);
    reduce_kernel<<<1, 1024>>>((float*)d_out, B);
}

// round 3
// speedup vs baseline: 1.2291x; 1.2291x over previous
#include <cuda_runtime.h>

#define KK 9
#define START_TAG 7
#define STOP_TAG 8
#define PD 8
#define FULLM 0xFFFFFFFFu

// deterministic per-sentence partials (no atomics) — B <= 8192 supported
__device__ float g_partial[8192];

__device__ __forceinline__ float dot9(const float* c, const float* v) {
    // 3-way chains: depth 3 FMA + 2 adds ~= 20cy, 11 instrs
    float d0 = c[0] * v[0];
    float d1 = c[1] * v[1];
    float d2 = c[2] * v[2];
    d0 = fmaf(c[3], v[3], d0);
    d1 = fmaf(c[4], v[4], d1);
    d2 = fmaf(c[5], v[5], d2);
    d0 = fmaf(c[6], v[6], d0);
    d1 = fmaf(c[7], v[7], d1);
    d2 = fmaf(c[8], v[8], d2);
    return (d0 + d1) + d2;
}

__device__ __forceinline__ float max9(const float* v) {
    float m = fmaxf(fmaxf(fmaxf(v[0], v[1]), fmaxf(v[2], v[3])),
                    fmaxf(fmaxf(v[4], v[5]), fmaxf(v[6], v[7])));
    return fmaxf(m, v[8]);
}

template <bool RESCALE>
__device__ __forceinline__ void step(float ef, const float* c, float* vec,
                                     float& s, int& eacc, int base, bool act) {
    float d  = dot9(c, vec);
    float ns = d * ef;
    if (RESCALE) {
        // power-of-two rescale from pre-step vec magnitude (exact)
        float m = max9(vec);
        int   e = ((__float_as_int(m) >> 23) & 0xFF) - 127;
        ns *= __int_as_float((127 - e) << 23);
        if (act) eacc += e;
    }
    if (act) s = ns;
#pragma unroll
    for (int k = 0; k < KK; ++k) vec[k] = __shfl_sync(FULLM, s, base + k);
}

__global__ void __launch_bounds__(32) crf_kernel(
    const float* __restrict__ feats, const float* __restrict__ trans,
    const int* __restrict__ tags, const int* __restrict__ lengths, int T) {
    const int b    = blockIdx.x;
    const int lane = threadIdx.x;
    const int len  = lengths[b];
    const float* __restrict__ f  = feats + (long)b * T * KK;
    const int* __restrict__  tg  = tags + (long)b * T;

    // ---------------- gold path score (all 32 lanes, parallel over t) -------
    float gold = 0.f;
    for (int t = lane; t < len; t += 32) {
        int cur  = tg[t];
        int prev = (t == 0) ? START_TAG : tg[t - 1];
        gold += trans[cur * KK + prev] + f[t * KK + cur];
    }
    if (lane == 0) gold += trans[STOP_TAG * KK + tg[len - 1]];
#pragma unroll
    for (int o = 16; o; o >>= 1) gold += __shfl_xor_sync(FULLM, gold, o);

    // ---------------- bidirectional exp-domain forward algorithm ------------
    // lanes 0..8  : forward scan over t = 0 .. NT-1       (rows of E)
    // lanes 16..24: backward scan over t = len-1 .. NT    (cols of E)
    const bool isb  = (lane & 16) != 0;
    const int  idx  = lane & 15;
    const int  base = lane & 16;
    const bool live = idx < KK;

    float c[KK];
#pragma unroll
    for (int k = 0; k < KK; ++k) {
        int   r  = isb ? k : idx;
        int   cc = isb ? idx : k;
        float tv = live ? trans[r * KK + cc] : 0.f;
        c[k]     = __expf(tv);  // exp(-10000) == 0 exactly in fp32
    }

    const int NT   = len >> 1;      // forward step count
    const int nbm1 = len - NT - 1;  // backward step count (inside loop)
    const int loop_main = (NT < nbm1) ? NT : nbm1;  // both dirs active
    const int nfull = loop_main & ~(PD - 1);

    float s;
    if (!isb) {
        s = (idx == START_TAG) ? 1.f : 0.f;
    } else {
        float tv = live ? trans[STOP_TAG * KK + idx] : 0.f;
        float fv = live ? f[(len - 1) * KK + idx] : 0.f;
        s        = live ? __expf(tv + fv) : 0.f;  // r0 = v_init * ef(len-1)
    }
    int   eacc = 0;
    float vec[KK];
#pragma unroll
    for (int k = 0; k < KK; ++k) vec[k] = __shfl_sync(FULLM, s, base + k);

    // prefetch ring in exp-domain (MUFU off the critical path)
    float buf[PD];
#pragma unroll
    for (int u = 0; u < PD; ++u) {
        int   t  = isb ? (len - 2 - u) : u;
        float fv = (live && t >= 0 && t < len) ? f[t * KK + idx] : 0.f;
        buf[u]   = __expf(fv);
    }
    // tail + epilogue values preloaded up front (no latency in the tail)
    float tbuf[PD];
#pragma unroll
    for (int u = 0; u < PD; ++u) {
        int   n  = nfull + u;
        int   t  = isb ? (len - 2 - n) : n;
        float fv = (live && t >= 0 && t < len) ? f[t * KK + idx] : 0.f;
        tbuf[u]  = __expf(fv);
    }

    for (int n0 = 0; n0 < nfull; n0 += PD) {
#pragma unroll
        for (int u = 0; u < PD; ++u) {
            float ef = buf[u];
            int   tp = isb ? (len - 2 - (n0 + u + PD)) : (n0 + u + PD);
            float fv = (live && tp >= 0 && tp < len) ? f[tp * KK + idx] : 0.f;
            buf[u]   = __expf(fv);
            if ((u & 3) == 3)
                step<true>(ef, c, vec, s, eacc, base, true);
            else
                step<false>(ef, c, vec, s, eacc, base, true);
        }
    }
    for (int n = nfull; n < loop_main; ++n) {
        float ef = tbuf[n - nfull];
        if ((n & 3) == 3)
            step<true>(ef, c, vec, s, eacc, base, true);
        else
            step<false>(ef, c, vec, s, eacc, base, true);
    }
    if (NT > loop_main) {  // len even: one forward-only epilogue step
        int   n  = loop_main;
        float ef = tbuf[n - nfull];
        if ((n & 3) == 3)
            step<true>(ef, c, vec, s, eacc, base, !isb);
        else
            step<false>(ef, c, vec, s, eacc, base, !isb);
    }

    // backward needs one final matrix application (no emission factor)
    float vfin = dot9(c, vec);
    // pull forward's u_i into backward lanes, combine: S = sum_i u_i * v_i
    float ui = __shfl_sync(FULLM, s, idx);
    float p  = (isb && live) ? vfin * ui : 0.f;
#pragma unroll
    for (int o = 16; o; o >>= 1) p += __shfl_xor_sync(FULLM, p, o);
    int eaf = __shfl_sync(FULLM, eacc, 0);
    int eab = __shfl_sync(FULLM, eacc, 16);

    if (lane == 0 && b < 8192) {
        float fwd    = (__log2f(p) + (float)(eaf + eab)) * 0.6931471805599453f;
        g_partial[b] = fwd - gold;
    }
}

__global__ void reduce_kernel(float* __restrict__ out, int B) {
    int   tid = threadIdx.x;
    float v   = 0.f;
    for (int i = tid; i < B; i += blockDim.x) v += g_partial[i];
#pragma unroll
    for (int o = 16; o; o >>= 1) v += __shfl_xor_sync(FULLM, v, o);
    __shared__ float sh[32];
    if ((tid & 31) == 0) sh[tid >> 5] = v;
    __syncthreads();
    if (tid < 32) {
        float w = (tid < (int)(blockDim.x >> 5)) ? sh[tid] : 0.f;
#pragma unroll
        for (int o = 16; o; o >>= 1) w += __shfl_xor_sync(FULLM, w, o);
        if (tid == 0) out[0] = w / (float)B;
    }
}

extern "C" void kernel_launch(void* const* d_in, const int* in_sizes, int n_in,
                              void* d_out, int out_size) {
    const float* feats   = (const float*)d_in[0];
    const float* trans   = (const float*)d_in[1];
    const int*   tags    = (const int*)d_in[2];
    const int*   lengths = (const int*)d_in[3];
    int B = in_sizes[3];
    int T = in_sizes[2] / B;
    crf_kernel<<<B, 32>>>(feats, trans, tags, lengths, T);
    reduce_kernel<<<1, 1024>>>((float*)d_out, B);
}